// round 13
// baseline (speedup 1.0000x reference)
#include <cuda_runtime.h>
#include <cuda_bf16.h>
#include <cstdint>

#define B_TOTAL 2048
#define N_TOTAL 100000
#define N_PAD   100096
#define F_DIM   16
#define TILE_M  512
#define CHUNK   128
#define NCHUNK  782           // 100096/128
#define NSPLIT  37            // grid 4 x 37 = 148 CTAs = 1/SM
#define THREADS 512

#define L2E  1.4426950408889634f
#define L2EH 0.72134752044448170f

// ---- per-chunk arena block layout (bytes) ----
#define XHo   0               // x hi bf16, 128 rows x 128B, swizzled tile image
#define XLo   16384
#define ATHo  32768           // alphaT hi [16][272B rows]
#define ATLo  37120
#define XSo   41472           // 128 f32 scaled norms
#define BLKSZ 41984
#define BLKOPS (BLKSZ / 16)   // 2624 x 16B cp.async ops

__device__ __align__(16) char g_arena[(size_t)NCHUNK * BLKSZ];
__device__ __nv_bfloat16 g_zh[B_TOTAL * 64];
__device__ __nv_bfloat16 g_zl[B_TOTAL * 64];
__device__ float         g_zs[B_TOTAL];
__device__ float         g_part[NSPLIT * B_TOTAL * F_DIM];

// ---- shared memory layout ----
#define SM_ZH   0             // z hi bf16 [512][64] swizzled, 64KB
#define SM_ZL   65536         // z lo, 64KB
#define SM_ZSN  131072        // 512 f32
#define SM_BLK  133120        // 2 bufs x BLKSZ
#define SMEM_BYTES (SM_BLK + 2 * BLKSZ)   // 217088

// ======================= helpers =======================
__device__ __forceinline__ uint32_t smem_u32(const void* p) {
    uint32_t a;
    asm("{ .reg .u64 t; cvta.to.shared.u64 t, %1; cvt.u32.u64 %0, t; }" : "=r"(a) : "l"(p));
    return a;
}
__device__ __forceinline__ void ldsm4(uint32_t r[4], uint32_t addr) {
    asm volatile("ldmatrix.sync.aligned.m8n8.x4.shared.b16 {%0,%1,%2,%3}, [%4];"
        : "=r"(r[0]), "=r"(r[1]), "=r"(r[2]), "=r"(r[3]) : "r"(addr));
}
__device__ __forceinline__ void mma_bf16(float c[4], const uint32_t a[4],
                                         uint32_t b0, uint32_t b1) {
    asm volatile("mma.sync.aligned.m16n8k16.row.col.f32.bf16.bf16.f32 "
        "{%0,%1,%2,%3}, {%4,%5,%6,%7}, {%8,%9}, {%0,%1,%2,%3};"
        : "+f"(c[0]), "+f"(c[1]), "+f"(c[2]), "+f"(c[3])
        : "r"(a[0]), "r"(a[1]), "r"(a[2]), "r"(a[3]), "r"(b0), "r"(b1));
}
__device__ __forceinline__ float ex2f(float x) {
    float r; asm("ex2.approx.ftz.f32 %0, %1;" : "=f"(r) : "f"(x)); return r;
}
__device__ __forceinline__ uint32_t pack_bf16(float hi, float lo) {
    __nv_bfloat162 t = __floats2bfloat162_rn(lo, hi);
    return *(uint32_t*)&t;
}
__device__ __forceinline__ void cpa16(uint32_t dst, const void* src) {
    asm volatile("cp.async.cg.shared.global [%0], [%1], 16;" :: "r"(dst), "l"(src));
}
__device__ __forceinline__ void cpa4(uint32_t dst, const void* src) {
    asm volatile("cp.async.ca.shared.global [%0], [%1], 4;" :: "r"(dst), "l"(src));
}
#define CP_COMMIT() asm volatile("cp.async.commit_group;" ::: "memory")
#define CP_WAIT0()  asm volatile("cp.async.wait_group 0;" ::: "memory")

// swizzled 16B-granule offset (tile image): c = 16B granule (0..7)
__device__ __forceinline__ uint32_t swz(int row, int c) {
    return (uint32_t)(row * 128 + ((c ^ (row & 7)) << 4));
}

// ======================= prep kernels =======================
// One warp per row: bf16 hi/lo split + scaled norm. x rows -> arena (pre-swizzled),
// z rows -> g_zh/g_zl/g_zs.
__global__ void prep_rows(const float* __restrict__ z, const float* __restrict__ dataset) {
    int r = (blockIdx.x * blockDim.x + threadIdx.x) >> 5;
    int l = threadIdx.x & 31;
    if (r < N_PAD) {
        float2 v = make_float2(0.f, 0.f);
        if (r < N_TOTAL) v = *(const float2*)(dataset + (size_t)r * 64 + 2 * l);
        float s = v.x * v.x + v.y * v.y;
        #pragma unroll
        for (int o = 16; o; o >>= 1) s += __shfl_xor_sync(0xffffffffu, s, o);
        __nv_bfloat162 h2 = __floats2bfloat162_rn(v.x, v.y);
        __nv_bfloat162 l2 = __floats2bfloat162_rn(v.x - __bfloat162float(h2.x),
                                                  v.y - __bfloat162float(h2.y));
        size_t blk = (size_t)(r >> 7) * BLKSZ;
        int rin = r & 127;
        uint32_t sw = (uint32_t)((((l >> 2) ^ (rin & 7)) << 4) | ((l & 3) * 4));
        *(uint32_t*)(g_arena + blk + XHo + rin * 128 + sw) = *(uint32_t*)&h2;
        *(uint32_t*)(g_arena + blk + XLo + rin * 128 + sw) = *(uint32_t*)&l2;
        if (l == 0)
            *(float*)(g_arena + blk + XSo + rin * 4) = (r < N_TOTAL) ? s * L2EH : 1e30f;
    } else if (r < N_PAD + B_TOTAL) {
        int q = r - N_PAD;
        float2 v = *(const float2*)(z + (size_t)q * 64 + 2 * l);
        float s = v.x * v.x + v.y * v.y;
        #pragma unroll
        for (int o = 16; o; o >>= 1) s += __shfl_xor_sync(0xffffffffu, s, o);
        __nv_bfloat162 h2 = __floats2bfloat162_rn(v.x, v.y);
        __nv_bfloat162 l2 = __floats2bfloat162_rn(v.x - __bfloat162float(h2.x),
                                                  v.y - __bfloat162float(h2.y));
        *(uint32_t*)(g_zh + (size_t)q * 64 + 2 * l) = *(uint32_t*)&h2;
        *(uint32_t*)(g_zl + (size_t)q * 64 + 2 * l) = *(uint32_t*)&l2;
        if (l == 0) g_zs[q] = s * L2EH;
    }
}

// One thread per n: transpose alpha into the arena's [16][272B] blocks, bf16 hi/lo.
__global__ void prep_at(const float* __restrict__ alpha) {
    int n = blockIdx.x * blockDim.x + threadIdx.x;
    if (n >= N_PAD) return;
    float v[16];
    if (n < N_TOTAL) {
        #pragma unroll
        for (int f = 0; f < 4; f++) {
            float4 t = *(const float4*)(alpha + (size_t)n * 16 + f * 4);
            v[4*f] = t.x; v[4*f+1] = t.y; v[4*f+2] = t.z; v[4*f+3] = t.w;
        }
    } else {
        #pragma unroll
        for (int f = 0; f < 16; f++) v[f] = 0.f;
    }
    size_t blk = (size_t)(n >> 7) * BLKSZ;
    int nin = n & 127;
    #pragma unroll
    for (int f = 0; f < 16; f++) {
        __nv_bfloat16 h = __float2bfloat16(v[f]);
        *(__nv_bfloat16*)(g_arena + blk + ATHo + f * 272 + nin * 2) = h;
        *(__nv_bfloat16*)(g_arena + blk + ATLo + f * 272 + nin * 2) =
            __float2bfloat16(v[f] - __bfloat162float(h));
    }
}

// ======================= main fused kernel =======================
extern __shared__ char smem_dyn[];

// stage one whole 42KB chunk block: 16B cp.async, contiguous src & dst
__device__ __forceinline__ void stage_blk(uint32_t dst, const char* src, int tid) {
    #pragma unroll
    for (int i = 0; i < 6; i++) {
        int idx = tid + THREADS * i;
        if (idx < BLKOPS) cpa16(dst + idx * 16, src + idx * 16);
    }
}

__global__ void __launch_bounds__(THREADS, 1)
rbf_main() {
    char* sm = smem_dyn;
    const uint32_t sb = smem_u32(sm);
    const int tid = threadIdx.x;
    const int l = tid & 31, w = tid >> 5;
    const int wm = w >> 1;          // 0..7 -> m32 within each m256 half
    const int wn = w & 1;           // 0..1 -> n64
    const int m0 = blockIdx.x * TILE_M;
    const int split = blockIdx.y;
    const int T = (NCHUNK - 1 - split) / NSPLIT + 1;

    // ---- prologue: z tiles (512 rows, hi/lo) + z norms (group 1) ----
    #pragma unroll
    for (int i = 0; i < 8; i++) {
        int idx = tid + THREADS * i;
        int row = idx >> 3, c = idx & 7;
        cpa16(sb + SM_ZH + swz(row, c), g_zh + (size_t)(m0 + row) * 64 + c * 8);
        cpa16(sb + SM_ZL + swz(row, c), g_zl + (size_t)(m0 + row) * 64 + c * 8);
    }
    cpa4(sb + SM_ZSN + tid * 4, g_zs + m0 + tid);
    CP_COMMIT();
    // chunk 0 (group 2)
    stage_blk(sb + SM_BLK, g_arena + (size_t)split * BLKSZ, tid);
    CP_COMMIT();
    CP_WAIT0();
    __syncthreads();

    const int g = l >> 2;

    // ldmatrix lane geometry
    const int la_row = wm * 32 + (l & 15);
    const int la_k   = l >> 4;
    const int lb_rw  = ((l >> 4) << 3) + (l & 7);
    const int lb_k   = (l >> 3) & 1;
    const int r7     = l & 7;
    const int lf_row = ((l >> 4) << 3) + (l & 7);

    float o[2][2][2][4] = {};   // [mh][mi][ft][4]
    int buf = 0;

    for (int t = 0; t < T; t++) {
        const uint32_t blk = sb + SM_BLK + buf * BLKSZ;

        // prefetch chunk t+1 into the other buffer; exactly one commit per iter
        if (t + 1 < T) {
            stage_blk(sb + SM_BLK + (buf ^ 1) * BLKSZ,
                      g_arena + (size_t)(split + (t + 1) * NSPLIT) * BLKSZ, tid);
        }
        CP_COMMIT();

        const uint32_t bXH = blk + XHo;
        const uint32_t bXL = blk + XLo;

        // ---- two m256 halves; per half: two n32 halves of GEMM1->exp->GEMM2 ----
        #pragma unroll
        for (int mh = 0; mh < 2; mh++) {
            const uint32_t baseZH = sb + SM_ZH + (mh * 256 + la_row) * 128;
            const uint32_t baseZL = sb + SM_ZL + (mh * 256 + la_row) * 128;

            #pragma unroll
            for (int nh = 0; nh < 2; nh++) {
                const uint32_t baseB = (uint32_t)((wn * 64 + nh * 32 + lb_rw) * 128);
                float cacc[2][4][4] = {};
                #pragma unroll
                for (int ks = 0; ks < 4; ks++) {
                    uint32_t offA = (uint32_t)(((ks * 2 + la_k) ^ r7) << 4);
                    uint32_t offB = (uint32_t)(((ks * 2 + lb_k) ^ r7) << 4);
                    uint32_t ah0[4], ah1[4], al0[4], al1[4];
                    ldsm4(ah0, baseZH + offA);
                    ldsm4(ah1, baseZH + 2048 + offA);
                    ldsm4(al0, baseZL + offA);
                    ldsm4(al1, baseZL + 2048 + offA);
                    #pragma unroll
                    for (int ng = 0; ng < 2; ng++) {
                        uint32_t bh[4], bl[4];
                        ldsm4(bh, bXH + baseB + ng * 2048 + offB);
                        ldsm4(bl, bXL + baseB + ng * 2048 + offB);
                        mma_bf16(cacc[0][2*ng],   ah0, bh[0], bh[1]);
                        mma_bf16(cacc[0][2*ng+1], ah0, bh[2], bh[3]);
                        mma_bf16(cacc[1][2*ng],   ah1, bh[0], bh[1]);
                        mma_bf16(cacc[1][2*ng+1], ah1, bh[2], bh[3]);
                        mma_bf16(cacc[0][2*ng],   al0, bh[0], bh[1]);
                        mma_bf16(cacc[0][2*ng+1], al0, bh[2], bh[3]);
                        mma_bf16(cacc[1][2*ng],   al1, bh[0], bh[1]);
                        mma_bf16(cacc[1][2*ng+1], al1, bh[2], bh[3]);
                        mma_bf16(cacc[0][2*ng],   ah0, bl[0], bl[1]);
                        mma_bf16(cacc[0][2*ng+1], ah0, bl[2], bl[3]);
                        mma_bf16(cacc[1][2*ng],   ah1, bl[0], bl[1]);
                        mma_bf16(cacc[1][2*ng+1], ah1, bl[2], bl[3]);
                    }
                }

                // z norms for this (mh, warp): loaded fresh (keeps live-regs low)
                float zz[2][2];
                {
                    int base = (mh * 256 + wm * 32 + g) * 4;
                    zz[0][0] = *(const float*)(sm + SM_ZSN + base);
                    zz[0][1] = *(const float*)(sm + SM_ZSN + base + 32);
                    zz[1][0] = *(const float*)(sm + SM_ZSN + base + 64);
                    zz[1][1] = *(const float*)(sm + SM_ZSN + base + 96);
                }

                // epilogue: w = exp2(c*log2e - zs' - xs'), split bf16 hi/lo, GEMM2 3-pass
                const uint32_t aTbh = blk + ATHo + lf_row * 272
                                    + (uint32_t)((wn * 64 + nh * 32 + lb_k * 8) * 2);
                const uint32_t aTbl = blk + ATLo + lf_row * 272
                                    + (uint32_t)((wn * 64 + nh * 32 + lb_k * 8) * 2);
                #pragma unroll
                for (int kg = 0; kg < 2; kg++) {
                    uint32_t ath[4], atl[4];
                    ldsm4(ath, aTbh + kg * 32);
                    ldsm4(atl, aTbl + kg * 32);
                    float2 xsp0 = *(const float2*)(sm + (blk - sb) + XSo +
                                  (wn * 64 + nh * 32 + (2 * kg) * 8 + (l & 3) * 2) * 4);
                    float2 xsp1 = *(const float2*)(sm + (blk - sb) + XSo +
                                  (wn * 64 + nh * 32 + (2 * kg + 1) * 8 + (l & 3) * 2) * 4);
                    #pragma unroll
                    for (int mi = 0; mi < 2; mi++) {
                        uint32_t fH[4], fL[4];
                        {
                            float* c = cacc[mi][2 * kg];
                            float w0 = ex2f(fmaf(c[0], L2E, -(zz[mi][0] + xsp0.x)));
                            float w1 = ex2f(fmaf(c[1], L2E, -(zz[mi][0] + xsp0.y)));
                            float w2 = ex2f(fmaf(c[2], L2E, -(zz[mi][1] + xsp0.x)));
                            float w3 = ex2f(fmaf(c[3], L2E, -(zz[mi][1] + xsp0.y)));
                            uint32_t p01 = pack_bf16(w1, w0);
                            uint32_t p23 = pack_bf16(w3, w2);
                            float h0 = __uint_as_float((p01 & 0xffffu) << 16);
                            float h1 = __uint_as_float(p01 & 0xffff0000u);
                            float h2 = __uint_as_float((p23 & 0xffffu) << 16);
                            float h3 = __uint_as_float(p23 & 0xffff0000u);
                            fH[0] = p01; fH[1] = p23;
                            fL[0] = pack_bf16(w1 - h1, w0 - h0);
                            fL[1] = pack_bf16(w3 - h3, w2 - h2);
                        }
                        {
                            float* c = cacc[mi][2 * kg + 1];
                            float w0 = ex2f(fmaf(c[0], L2E, -(zz[mi][0] + xsp1.x)));
                            float w1 = ex2f(fmaf(c[1], L2E, -(zz[mi][0] + xsp1.y)));
                            float w2 = ex2f(fmaf(c[2], L2E, -(zz[mi][1] + xsp1.x)));
                            float w3 = ex2f(fmaf(c[3], L2E, -(zz[mi][1] + xsp1.y)));
                            uint32_t p01 = pack_bf16(w1, w0);
                            uint32_t p23 = pack_bf16(w3, w2);
                            float h0 = __uint_as_float((p01 & 0xffffu) << 16);
                            float h1 = __uint_as_float(p01 & 0xffff0000u);
                            float h2 = __uint_as_float((p23 & 0xffffu) << 16);
                            float h3 = __uint_as_float(p23 & 0xffff0000u);
                            fH[2] = p01; fH[3] = p23;
                            fL[2] = pack_bf16(w1 - h1, w0 - h0);
                            fL[3] = pack_bf16(w3 - h3, w2 - h2);
                        }
                        mma_bf16(o[mh][mi][0], fH, ath[0], ath[1]);
                        mma_bf16(o[mh][mi][1], fH, ath[2], ath[3]);
                        mma_bf16(o[mh][mi][0], fL, ath[0], ath[1]);
                        mma_bf16(o[mh][mi][1], fL, ath[2], ath[3]);
                        mma_bf16(o[mh][mi][0], fH, atl[0], atl[1]);
                        mma_bf16(o[mh][mi][1], fH, atl[2], atl[3]);
                    }
                }
            }
        }

        CP_WAIT0();             // chunk t+1 fully landed
        __syncthreads();
        buf ^= 1;
    }

    // ---- reduce across the 2 wn warps, write partials ----
    float* red = (float*)sm;                 // [512][16] f32, reuses z-tile space
    if (wn == 1) {
        #pragma unroll
        for (int mh = 0; mh < 2; mh++)
            #pragma unroll
            for (int mi = 0; mi < 2; mi++)
                #pragma unroll
                for (int ft = 0; ft < 2; ft++) {
                    int mr = mh * 256 + wm * 32 + mi * 16 + g;
                    int f0 = ft * 8 + (l & 3) * 2;
                    *(float2*)(red + mr * 16 + f0) =
                        make_float2(o[mh][mi][ft][0], o[mh][mi][ft][1]);
                    *(float2*)(red + (mr + 8) * 16 + f0) =
                        make_float2(o[mh][mi][ft][2], o[mh][mi][ft][3]);
                }
    }
    __syncthreads();
    if (wn == 0) {
        float* dst = g_part + ((size_t)split * B_TOTAL + m0) * F_DIM;
        #pragma unroll
        for (int mh = 0; mh < 2; mh++)
            #pragma unroll
            for (int mi = 0; mi < 2; mi++)
                #pragma unroll
                for (int ft = 0; ft < 2; ft++) {
                    int mr = mh * 256 + wm * 32 + mi * 16 + g;
                    int f0 = ft * 8 + (l & 3) * 2;
                    float2 a = *(float2*)(red + mr * 16 + f0);
                    float2 b = *(float2*)(red + (mr + 8) * 16 + f0);
                    *(float2*)(dst + mr * 16 + f0) =
                        make_float2(o[mh][mi][ft][0] + a.x, o[mh][mi][ft][1] + a.y);
                    *(float2*)(dst + (mr + 8) * 16 + f0) =
                        make_float2(o[mh][mi][ft][2] + b.x, o[mh][mi][ft][3] + b.y);
                }
    }
}

// Deterministic reduction of the NSPLIT partial buffers.
__global__ void rbf_reduce(float* __restrict__ out) {
    int gid = blockIdx.x * blockDim.x + threadIdx.x;
    if (gid >= B_TOTAL * F_DIM) return;
    float s = 0.f;
    #pragma unroll
    for (int c = 0; c < NSPLIT; c++) s += g_part[(size_t)c * (B_TOTAL * F_DIM) + gid];
    out[gid] = s;
}

extern "C" void kernel_launch(void* const* d_in, const int* in_sizes, int n_in,
                              void* d_out, int out_size) {
    const float* z       = (const float*)d_in[0];   // [2048, 64]
    const float* dataset = (const float*)d_in[1];   // [100000, 64]
    const float* alpha   = (const float*)d_in[2];   // [100000, 16]
    float* out = (float*)d_out;                     // [2048, 16]
    (void)in_sizes; (void)n_in; (void)out_size;

    const int rows = N_PAD + B_TOTAL;
    prep_rows<<<(rows * 32 + 255) / 256, 256>>>(z, dataset);
    prep_at<<<(N_PAD + 255) / 256, 256>>>(alpha);

    cudaFuncSetAttribute(rbf_main, cudaFuncAttributeMaxDynamicSharedMemorySize, SMEM_BYTES);
    dim3 grid(B_TOTAL / TILE_M, NSPLIT);
    rbf_main<<<grid, THREADS, SMEM_BYTES>>>();
    rbf_reduce<<<(B_TOTAL * F_DIM + 255) / 256, 256>>>(out);
}

// round 15
// speedup vs baseline: 2.3375x; 2.3375x over previous
#include <cuda_runtime.h>
#include <cuda_bf16.h>
#include <cstdint>

#define B_TOTAL 2048
#define N_TOTAL 100000
#define CHUNK   192
#define NCHUNK  522           // ceil(100000/192)
#define N_PAD   (NCHUNK * CHUNK)   // 100224
#define F_DIM   16
#define TILE_M  256
#define NSPLIT  18            // grid 8 x 18 = 144 CTAs
#define THREADS 512

#define L2E  1.4426950408889634f
#define L2EH 0.72134752044448170f

// ---- per-chunk arena block layout (bytes) ----
#define XHo   0               // x hi bf16, 192 rows x 128B, swizzled tile image
#define XLo   24576
#define ATHo  49152           // alphaT hi [16][400B rows]
#define ATLo  55552
#define XSo   61952           // 192 f32 scaled norms
#define BLKSZ 62720
#define BLKOPS (BLKSZ / 16)   // 3920 x 16B cp.async ops

__device__ __align__(16) char g_arena[(size_t)NCHUNK * BLKSZ];
__device__ __nv_bfloat16 g_zh[B_TOTAL * 64];
__device__ __nv_bfloat16 g_zl[B_TOTAL * 64];
__device__ float         g_zs[B_TOTAL];
__device__ float         g_part[NSPLIT * B_TOTAL * F_DIM];

// ---- shared memory layout ----
#define SM_ZH   0             // z hi bf16 [256][64] swizzled, 32KB
#define SM_ZL   32768
#define SM_ZSN  65536         // 256 f32
#define SM_BLK  66560         // 2 bufs x BLKSZ
#define SMEM_BYTES (SM_BLK + 2 * BLKSZ)   // 192000

// ======================= helpers =======================
__device__ __forceinline__ uint32_t smem_u32(const void* p) {
    uint32_t a;
    asm("{ .reg .u64 t; cvta.to.shared.u64 t, %1; cvt.u32.u64 %0, t; }" : "=r"(a) : "l"(p));
    return a;
}
__device__ __forceinline__ void ldsm4(uint32_t r[4], uint32_t addr) {
    asm volatile("ldmatrix.sync.aligned.m8n8.x4.shared.b16 {%0,%1,%2,%3}, [%4];"
        : "=r"(r[0]), "=r"(r[1]), "=r"(r[2]), "=r"(r[3]) : "r"(addr));
}
__device__ __forceinline__ void mma_bf16(float c[4], const uint32_t a[4],
                                         uint32_t b0, uint32_t b1) {
    asm volatile("mma.sync.aligned.m16n8k16.row.col.f32.bf16.bf16.f32 "
        "{%0,%1,%2,%3}, {%4,%5,%6,%7}, {%8,%9}, {%0,%1,%2,%3};"
        : "+f"(c[0]), "+f"(c[1]), "+f"(c[2]), "+f"(c[3])
        : "r"(a[0]), "r"(a[1]), "r"(a[2]), "r"(a[3]), "r"(b0), "r"(b1));
}
__device__ __forceinline__ float ex2f(float x) {
    float r; asm("ex2.approx.ftz.f32 %0, %1;" : "=f"(r) : "f"(x)); return r;
}
__device__ __forceinline__ uint32_t pack_bf16(float hi, float lo) {
    __nv_bfloat162 t = __floats2bfloat162_rn(lo, hi);
    return *(uint32_t*)&t;
}
__device__ __forceinline__ void cpa16(uint32_t dst, const void* src) {
    asm volatile("cp.async.cg.shared.global [%0], [%1], 16;" :: "r"(dst), "l"(src));
}
__device__ __forceinline__ void cpa4(uint32_t dst, const void* src) {
    asm volatile("cp.async.ca.shared.global [%0], [%1], 4;" :: "r"(dst), "l"(src));
}
#define CP_COMMIT() asm volatile("cp.async.commit_group;" ::: "memory")
#define CP_WAIT0()  asm volatile("cp.async.wait_group 0;" ::: "memory")

// swizzled 16B-granule offset (tile image): c = 16B granule (0..7)
__device__ __forceinline__ uint32_t swz(int row, int c) {
    return (uint32_t)(row * 128 + ((c ^ (row & 7)) << 4));
}

// ======================= prep kernels =======================
// One warp per row: bf16 hi/lo split + scaled norm. x rows -> arena (pre-swizzled),
// z rows -> g_zh/g_zl/g_zs.
__global__ void prep_rows(const float* __restrict__ z, const float* __restrict__ dataset) {
    int r = (blockIdx.x * blockDim.x + threadIdx.x) >> 5;
    int l = threadIdx.x & 31;
    if (r < N_PAD) {
        float2 v = make_float2(0.f, 0.f);
        if (r < N_TOTAL) v = *(const float2*)(dataset + (size_t)r * 64 + 2 * l);
        float s = v.x * v.x + v.y * v.y;
        #pragma unroll
        for (int o = 16; o; o >>= 1) s += __shfl_xor_sync(0xffffffffu, s, o);
        __nv_bfloat162 h2 = __floats2bfloat162_rn(v.x, v.y);
        __nv_bfloat162 l2 = __floats2bfloat162_rn(v.x - __bfloat162float(h2.x),
                                                  v.y - __bfloat162float(h2.y));
        int cidx = r / CHUNK;
        int rin  = r - cidx * CHUNK;
        size_t blk = (size_t)cidx * BLKSZ;
        uint32_t sw = (uint32_t)((((l >> 2) ^ (rin & 7)) << 4) | ((l & 3) * 4));
        *(uint32_t*)(g_arena + blk + XHo + rin * 128 + sw) = *(uint32_t*)&h2;
        *(uint32_t*)(g_arena + blk + XLo + rin * 128 + sw) = *(uint32_t*)&l2;
        if (l == 0)
            *(float*)(g_arena + blk + XSo + rin * 4) = (r < N_TOTAL) ? s * L2EH : 1e30f;
    } else if (r < N_PAD + B_TOTAL) {
        int q = r - N_PAD;
        float2 v = *(const float2*)(z + (size_t)q * 64 + 2 * l);
        float s = v.x * v.x + v.y * v.y;
        #pragma unroll
        for (int o = 16; o; o >>= 1) s += __shfl_xor_sync(0xffffffffu, s, o);
        __nv_bfloat162 h2 = __floats2bfloat162_rn(v.x, v.y);
        __nv_bfloat162 l2 = __floats2bfloat162_rn(v.x - __bfloat162float(h2.x),
                                                  v.y - __bfloat162float(h2.y));
        *(uint32_t*)(g_zh + (size_t)q * 64 + 2 * l) = *(uint32_t*)&h2;
        *(uint32_t*)(g_zl + (size_t)q * 64 + 2 * l) = *(uint32_t*)&l2;
        if (l == 0) g_zs[q] = s * L2EH;
    }
}

// One thread per n: transpose alpha into the arena's [16][400B] blocks, bf16 hi/lo.
__global__ void prep_at(const float* __restrict__ alpha) {
    int n = blockIdx.x * blockDim.x + threadIdx.x;
    if (n >= N_PAD) return;
    float v[16];
    if (n < N_TOTAL) {
        #pragma unroll
        for (int f = 0; f < 4; f++) {
            float4 t = *(const float4*)(alpha + (size_t)n * 16 + f * 4);
            v[4*f] = t.x; v[4*f+1] = t.y; v[4*f+2] = t.z; v[4*f+3] = t.w;
        }
    } else {
        #pragma unroll
        for (int f = 0; f < 16; f++) v[f] = 0.f;
    }
    int cidx = n / CHUNK;
    int nin  = n - cidx * CHUNK;
    size_t blk = (size_t)cidx * BLKSZ;
    #pragma unroll
    for (int f = 0; f < 16; f++) {
        __nv_bfloat16 h = __float2bfloat16(v[f]);
        *(__nv_bfloat16*)(g_arena + blk + ATHo + f * 400 + nin * 2) = h;
        *(__nv_bfloat16*)(g_arena + blk + ATLo + f * 400 + nin * 2) =
            __float2bfloat16(v[f] - __bfloat162float(h));
    }
}

// ======================= main fused kernel =======================
extern __shared__ char smem_dyn[];

// stage one whole chunk block: 16B cp.async, contiguous src & dst
__device__ __forceinline__ void stage_blk(uint32_t dst, const char* src, int tid) {
    #pragma unroll
    for (int i = 0; i < 8; i++) {
        int idx = tid + THREADS * i;
        if (idx < BLKOPS) cpa16(dst + idx * 16, src + idx * 16);
    }
}

__global__ void __launch_bounds__(THREADS, 1)
rbf_main() {
    char* sm = smem_dyn;
    const uint32_t sb = smem_u32(sm);
    const int tid = threadIdx.x;
    const int l = tid & 31, w = tid >> 5;
    const int wm = w >> 1;          // 0..7 -> m32
    const int wn = w & 1;           // 0..1 -> n96
    const int m0 = blockIdx.x * TILE_M;
    const int split = blockIdx.y;
    const int T = (NCHUNK - 1 - split) / NSPLIT + 1;

    // ---- prologue: z tiles + z norms (group 1) ----
    #pragma unroll
    for (int i = 0; i < 4; i++) {
        int idx = tid + THREADS * i;
        int row = idx >> 3, c = idx & 7;
        cpa16(sb + SM_ZH + swz(row, c), g_zh + (size_t)(m0 + row) * 64 + c * 8);
        cpa16(sb + SM_ZL + swz(row, c), g_zl + (size_t)(m0 + row) * 64 + c * 8);
    }
    if (tid < 256) cpa4(sb + SM_ZSN + tid * 4, g_zs + m0 + tid);
    CP_COMMIT();
    // chunk 0 (group 2)
    stage_blk(sb + SM_BLK, g_arena + (size_t)split * BLKSZ, tid);
    CP_COMMIT();
    CP_WAIT0();
    __syncthreads();

    const int g = l >> 2;
    float zsv[2][2];
    #pragma unroll
    for (int mi = 0; mi < 2; mi++) {
        zsv[mi][0] = *(const float*)(sm + SM_ZSN + (wm * 32 + mi * 16 + g) * 4);
        zsv[mi][1] = *(const float*)(sm + SM_ZSN + (wm * 32 + mi * 16 + g + 8) * 4);
    }

    // ldmatrix lane geometry
    const int la_row = wm * 32 + (l & 15);
    const int la_k   = l >> 4;
    const int lb_rw  = ((l >> 4) << 3) + (l & 7);
    const int lb_k   = (l >> 3) & 1;
    const int r7     = l & 7;
    const uint32_t baseZH = sb + SM_ZH + la_row * 128;
    const uint32_t baseZL = sb + SM_ZL + la_row * 128;
    const int lf_row = ((l >> 4) << 3) + (l & 7);

    float o[2][2][4] = {};
    int buf = 0;

    for (int t = 0; t < T; t++) {
        const uint32_t blk = sb + SM_BLK + buf * BLKSZ;

        // prefetch chunk t+1 into the other buffer; exactly one commit per iter
        if (t + 1 < T) {
            stage_blk(sb + SM_BLK + (buf ^ 1) * BLKSZ,
                      g_arena + (size_t)(split + (t + 1) * NSPLIT) * BLKSZ, tid);
        }
        CP_COMMIT();

        const uint32_t bXH = blk + XHo;
        const uint32_t bXL = blk + XLo;

        // ---- three n32 halves: GEMM1 (bf16 3-pass) -> exp -> GEMM2 (bf16 3-pass) ----
        #pragma unroll
        for (int nh = 0; nh < 3; nh++) {
            const uint32_t baseB = (uint32_t)((wn * 96 + nh * 32 + lb_rw) * 128);
            float cacc[2][4][4] = {};
            #pragma unroll
            for (int ks = 0; ks < 4; ks++) {
                uint32_t offA = (uint32_t)(((ks * 2 + la_k) ^ r7) << 4);
                uint32_t offB = (uint32_t)(((ks * 2 + lb_k) ^ r7) << 4);
                uint32_t ah0[4], ah1[4], al0[4], al1[4];
                ldsm4(ah0, baseZH + offA);
                ldsm4(ah1, baseZH + 2048 + offA);
                ldsm4(al0, baseZL + offA);
                ldsm4(al1, baseZL + 2048 + offA);
                #pragma unroll
                for (int ng = 0; ng < 2; ng++) {
                    uint32_t bh[4], bl[4];
                    ldsm4(bh, bXH + baseB + ng * 2048 + offB);
                    ldsm4(bl, bXL + baseB + ng * 2048 + offB);
                    mma_bf16(cacc[0][2*ng],   ah0, bh[0], bh[1]);
                    mma_bf16(cacc[0][2*ng+1], ah0, bh[2], bh[3]);
                    mma_bf16(cacc[1][2*ng],   ah1, bh[0], bh[1]);
                    mma_bf16(cacc[1][2*ng+1], ah1, bh[2], bh[3]);
                    mma_bf16(cacc[0][2*ng],   al0, bh[0], bh[1]);
                    mma_bf16(cacc[0][2*ng+1], al0, bh[2], bh[3]);
                    mma_bf16(cacc[1][2*ng],   al1, bh[0], bh[1]);
                    mma_bf16(cacc[1][2*ng+1], al1, bh[2], bh[3]);
                    mma_bf16(cacc[0][2*ng],   ah0, bl[0], bl[1]);
                    mma_bf16(cacc[0][2*ng+1], ah0, bl[2], bl[3]);
                    mma_bf16(cacc[1][2*ng],   ah1, bl[0], bl[1]);
                    mma_bf16(cacc[1][2*ng+1], ah1, bl[2], bl[3]);
                }
            }

            // epilogue: w = exp2(c*log2e - zs' - xs'), split bf16 hi/lo, GEMM2 3-pass
            const uint32_t aTbh = blk + ATHo + lf_row * 400
                                + (uint32_t)((wn * 96 + nh * 32 + lb_k * 8) * 2);
            const uint32_t aTbl = blk + ATLo + lf_row * 400
                                + (uint32_t)((wn * 96 + nh * 32 + lb_k * 8) * 2);
            #pragma unroll
            for (int kg = 0; kg < 2; kg++) {
                uint32_t fH[2][4], fL[2][4];
                #pragma unroll
                for (int q = 0; q < 2; q++) {
                    int nt = 2 * kg + q;
                    float2 xsp = *(const float2*)(sm + (blk - sb) + XSo +
                                  (wn * 96 + nh * 32 + nt * 8 + (l & 3) * 2) * 4);
                    #pragma unroll
                    for (int mi = 0; mi < 2; mi++) {
                        float* c = cacc[mi][nt];
                        float w0 = ex2f(fmaf(c[0], L2E, -(zsv[mi][0] + xsp.x)));
                        float w1 = ex2f(fmaf(c[1], L2E, -(zsv[mi][0] + xsp.y)));
                        float w2 = ex2f(fmaf(c[2], L2E, -(zsv[mi][1] + xsp.x)));
                        float w3 = ex2f(fmaf(c[3], L2E, -(zsv[mi][1] + xsp.y)));
                        uint32_t p01 = pack_bf16(w1, w0);
                        uint32_t p23 = pack_bf16(w3, w2);
                        float h0 = __uint_as_float((p01 & 0xffffu) << 16);
                        float h1 = __uint_as_float(p01 & 0xffff0000u);
                        float h2 = __uint_as_float((p23 & 0xffffu) << 16);
                        float h3 = __uint_as_float(p23 & 0xffff0000u);
                        fH[mi][2*q]   = p01;
                        fH[mi][2*q+1] = p23;
                        fL[mi][2*q]   = pack_bf16(w1 - h1, w0 - h0);
                        fL[mi][2*q+1] = pack_bf16(w3 - h3, w2 - h2);
                    }
                }
                uint32_t ath[4], atl[4];
                ldsm4(ath, aTbh + kg * 32);
                ldsm4(atl, aTbl + kg * 32);
                #pragma unroll
                for (int mi = 0; mi < 2; mi++) {
                    mma_bf16(o[mi][0], fH[mi], ath[0], ath[1]);
                    mma_bf16(o[mi][1], fH[mi], ath[2], ath[3]);
                    mma_bf16(o[mi][0], fL[mi], ath[0], ath[1]);
                    mma_bf16(o[mi][1], fL[mi], ath[2], ath[3]);
                    mma_bf16(o[mi][0], fH[mi], atl[0], atl[1]);
                    mma_bf16(o[mi][1], fH[mi], atl[2], atl[3]);
                }
            }
        }

        CP_WAIT0();             // chunk t+1 fully landed
        __syncthreads();
        buf ^= 1;
    }

    // ---- reduce across the 2 wn warps, write partials ----
    float* red = (float*)sm;                 // [256][16] f32, reuses z-tile space
    if (wn == 1) {
        #pragma unroll
        for (int mi = 0; mi < 2; mi++)
            #pragma unroll
            for (int ft = 0; ft < 2; ft++) {
                int mr = wm * 32 + mi * 16 + g;
                int f0 = ft * 8 + (l & 3) * 2;
                *(float2*)(red + mr * 16 + f0)       = make_float2(o[mi][ft][0], o[mi][ft][1]);
                *(float2*)(red + (mr + 8) * 16 + f0) = make_float2(o[mi][ft][2], o[mi][ft][3]);
            }
    }
    __syncthreads();
    if (wn == 0) {
        float* dst = g_part + ((size_t)split * B_TOTAL + m0) * F_DIM;
        #pragma unroll
        for (int mi = 0; mi < 2; mi++)
            #pragma unroll
            for (int ft = 0; ft < 2; ft++) {
                int mr = wm * 32 + mi * 16 + g;
                int f0 = ft * 8 + (l & 3) * 2;
                float2 a = *(float2*)(red + mr * 16 + f0);
                float2 b = *(float2*)(red + (mr + 8) * 16 + f0);
                *(float2*)(dst + mr * 16 + f0) =
                    make_float2(o[mi][ft][0] + a.x, o[mi][ft][1] + a.y);
                *(float2*)(dst + (mr + 8) * 16 + f0) =
                    make_float2(o[mi][ft][2] + b.x, o[mi][ft][3] + b.y);
            }
    }
}

// Deterministic reduction of the NSPLIT partial buffers.
__global__ void rbf_reduce(float* __restrict__ out) {
    int gid = blockIdx.x * blockDim.x + threadIdx.x;
    if (gid >= B_TOTAL * F_DIM) return;
    float s = 0.f;
    #pragma unroll
    for (int c = 0; c < NSPLIT; c++) s += g_part[(size_t)c * (B_TOTAL * F_DIM) + gid];
    out[gid] = s;
}

extern "C" void kernel_launch(void* const* d_in, const int* in_sizes, int n_in,
                              void* d_out, int out_size) {
    const float* z       = (const float*)d_in[0];   // [2048, 64]
    const float* dataset = (const float*)d_in[1];   // [100000, 64]
    const float* alpha   = (const float*)d_in[2];   // [100000, 16]
    float* out = (float*)d_out;                     // [2048, 16]
    (void)in_sizes; (void)n_in; (void)out_size;

    const int rows = N_PAD + B_TOTAL;
    prep_rows<<<(rows * 32 + 255) / 256, 256>>>(z, dataset);
    prep_at<<<(N_PAD + 255) / 256, 256>>>(alpha);

    cudaFuncSetAttribute(rbf_main, cudaFuncAttributeMaxDynamicSharedMemorySize, SMEM_BYTES);
    dim3 grid(B_TOTAL / TILE_M, NSPLIT);
    rbf_main<<<grid, THREADS, SMEM_BYTES>>>();
    rbf_reduce<<<(B_TOTAL * F_DIM + 255) / 256, 256>>>(out);
}